// round 1
// baseline (speedup 1.0000x reference)
#include <cuda_runtime.h>
#include <cuda_bf16.h>
#include <cstdint>

#define MAX_NODES 100000
#define HID 64          // hidden/output feature dim (both layers)
#define IN_DIM 256

// Scratch (allocation-free rule: device globals)
__device__ float g_h[(size_t)MAX_NODES * HID];    // feature buffer A
__device__ float g_agg[(size_t)MAX_NODES * HID];  // feature buffer B
__device__ float g_dis[MAX_NODES];                // deg^{-1/2}
__device__ int   g_deg[MAX_NODES];

// ---------------------------------------------------------------------------
// degree / normalization
// ---------------------------------------------------------------------------
__global__ void k_init_deg(int M) {
    int i = blockIdx.x * blockDim.x + threadIdx.x;
    if (i < M) g_deg[i] = 1;  // self loop
}

__global__ void k_count_deg(const int* __restrict__ dst, int E) {
    int e = blockIdx.x * blockDim.x + threadIdx.x;
    if (e < E) atomicAdd(&g_deg[dst[e]], 1);
}

__global__ void k_dis(int M) {
    int i = blockIdx.x * blockDim.x + threadIdx.x;
    if (i < M) g_dis[i] = rsqrtf((float)g_deg[i]);
}

// ---------------------------------------------------------------------------
// GEMM: C[M x 64] = A[M x K] * B[K x 64]   (K multiple of 32)
// BM=128, BN=64, BK=32, 256 threads, each thread 8x4 outputs.
// ---------------------------------------------------------------------------
#define BM 128
#define BN 64
#define BK 32
#define TM 8
#define TN 4

__global__ __launch_bounds__(256) void k_gemm(
    const float* __restrict__ A, const float* __restrict__ B,
    float* __restrict__ C, int M, int K)
{
    __shared__ float As[BK][BM + 4];   // transposed A tile, padded
    __shared__ float Bs[BK][BN];

    int tid = threadIdx.x;
    int ty = tid >> 4;        // 0..15 -> row group
    int tx = tid & 15;        // 0..15 -> col group
    int blockRow = blockIdx.x * BM;

    // A-tile load map: 16 floats/thread = 4 x float4
    int la_r = tid >> 3;             // 0..31
    int la_c = (tid & 7) * 4;        // 0..28
    // B-tile load map: 8 floats/thread = 2 x float4
    int lb_r = tid >> 4;             // 0..15
    int lb_c = (tid & 15) * 4;

    float acc[TM][TN];
    #pragma unroll
    for (int i = 0; i < TM; i++)
        #pragma unroll
        for (int j = 0; j < TN; j++) acc[i][j] = 0.f;

    for (int k0 = 0; k0 < K; k0 += BK) {
        #pragma unroll
        for (int p = 0; p < 4; p++) {
            int r = la_r + 32 * p;
            int gr = blockRow + r;
            float4 v = make_float4(0.f, 0.f, 0.f, 0.f);
            if (gr < M) v = *(const float4*)(A + (size_t)gr * K + k0 + la_c);
            As[la_c + 0][r] = v.x;
            As[la_c + 1][r] = v.y;
            As[la_c + 2][r] = v.z;
            As[la_c + 3][r] = v.w;
        }
        #pragma unroll
        for (int p = 0; p < 2; p++) {
            int r = lb_r + 16 * p;
            *(float4*)&Bs[r][lb_c] = *(const float4*)(B + (size_t)(k0 + r) * BN + lb_c);
        }
        __syncthreads();

        #pragma unroll
        for (int k = 0; k < BK; k++) {
            float a[TM], b[TN];
            float4 a0 = *(const float4*)&As[k][ty * TM];
            float4 a1 = *(const float4*)&As[k][ty * TM + 4];
            a[0] = a0.x; a[1] = a0.y; a[2] = a0.z; a[3] = a0.w;
            a[4] = a1.x; a[5] = a1.y; a[6] = a1.z; a[7] = a1.w;
            float4 bv = *(const float4*)&Bs[k][tx * TN];
            b[0] = bv.x; b[1] = bv.y; b[2] = bv.z; b[3] = bv.w;
            #pragma unroll
            for (int i = 0; i < TM; i++)
                #pragma unroll
                for (int j = 0; j < TN; j++)
                    acc[i][j] += a[i] * b[j];
        }
        __syncthreads();
    }

    #pragma unroll
    for (int i = 0; i < TM; i++) {
        int gr = blockRow + ty * TM + i;
        if (gr < M) {
            float4 v = make_float4(acc[i][0], acc[i][1], acc[i][2], acc[i][3]);
            *(float4*)(C + (size_t)gr * HID + tx * TN) = v;
        }
    }
}

// ---------------------------------------------------------------------------
// agg init: out[i] = dis[i]^2 * h[i] + bias    (self-loop term + bias)
// threads = M*16, each handles one float4 of the 64-wide row
// ---------------------------------------------------------------------------
__global__ void k_init_agg(const float* __restrict__ h, const float* __restrict__ bias,
                           float* __restrict__ out, int M)
{
    int t = blockIdx.x * blockDim.x + threadIdx.x;
    if (t >= M * 16) return;
    int i = t >> 4, q = t & 15;
    float d = g_dis[i];
    float w = d * d;
    float4 v = *(const float4*)(h + (size_t)i * HID + q * 4);
    float4 bq = *(const float4*)(bias + q * 4);
    v.x = w * v.x + bq.x; v.y = w * v.y + bq.y;
    v.z = w * v.z + bq.z; v.w = w * v.w + bq.w;
    *(float4*)(out + (size_t)i * HID + q * 4) = v;
}

// ---------------------------------------------------------------------------
// push scatter: out[dst] += dis[src]*dis[dst] * h[src]
// 16 threads per edge (one float4 each) -> coalesced gather + RED.128
// ---------------------------------------------------------------------------
__global__ void k_scatter(const float* __restrict__ h, const int* __restrict__ src,
                          const int* __restrict__ dst, float* __restrict__ out, int E)
{
    long long t = (long long)blockIdx.x * blockDim.x + threadIdx.x;
    if (t >= (long long)E * 16) return;
    int e = (int)(t >> 4);
    int q = (int)(t & 15);
    int s = __ldg(src + e);
    int d = __ldg(dst + e);
    float w = __ldg(g_dis + s) * __ldg(g_dis + d);
    float4 v = *(const float4*)(h + (size_t)s * HID + q * 4);
    v.x *= w; v.y *= w; v.z *= w; v.w *= w;
    atomicAdd((float4*)(out + (size_t)d * HID + q * 4), v);
}

// ---------------------------------------------------------------------------
// relu: h = max(agg, 0)
// ---------------------------------------------------------------------------
__global__ void k_relu(const float* __restrict__ in, float* __restrict__ out, int M) {
    int t = blockIdx.x * blockDim.x + threadIdx.x;
    if (t >= M * 16) return;
    float4 v = *(const float4*)(in + (size_t)t * 4);
    v.x = fmaxf(v.x, 0.f); v.y = fmaxf(v.y, 0.f);
    v.z = fmaxf(v.z, 0.f); v.w = fmaxf(v.w, 0.f);
    *(float4*)(out + (size_t)t * 4) = v;
}

// ---------------------------------------------------------------------------
extern "C" void kernel_launch(void* const* d_in, const int* in_sizes, int n_in,
                              void* d_out, int out_size)
{
    const float* x  = (const float*)d_in[0];
    const int*   ei = (const int*)d_in[1];
    const float* W1 = (const float*)d_in[2];
    const float* b1 = (const float*)d_in[3];
    const float* W2 = (const float*)d_in[4];
    const float* b2 = (const float*)d_in[5];
    float* out = (float*)d_out;

    int M = in_sizes[0] / IN_DIM;
    int E = in_sizes[1] / 2;
    const int* src = ei;
    const int* dst = ei + E;

    float *ph, *pagg;
    cudaGetSymbolAddress((void**)&ph, g_h);
    cudaGetSymbolAddress((void**)&pagg, g_agg);

    int tb = 256;
    int gM   = (M + tb - 1) / tb;
    int gE   = (E + tb - 1) / tb;
    int gM16 = (M * 16 + tb - 1) / tb;
    long long e16 = (long long)E * 16;
    int gE16 = (int)((e16 + tb - 1) / tb);
    int gGemm = (M + BM - 1) / BM;

    // normalization
    k_init_deg<<<gM, tb>>>(M);
    k_count_deg<<<gE, tb>>>(dst, E);
    k_dis<<<gM, tb>>>(M);

    // layer 1: h1 = x @ W1 ; agg1 = A_norm h1 + b1 ; h = relu(agg1)
    k_gemm<<<gGemm, tb>>>(x, W1, ph, M, IN_DIM);
    k_init_agg<<<gM16, tb>>>(ph, b1, pagg, M);
    k_scatter<<<gE16, tb>>>(ph, src, dst, pagg, E);
    k_relu<<<gM16, tb>>>(pagg, ph, M);

    // layer 2: h2 = h @ W2 ; out = A_norm h2 + b2
    k_gemm<<<gGemm, tb>>>(ph, W2, pagg, M, HID);
    k_init_agg<<<gM16, tb>>>(pagg, b2, out, M);
    k_scatter<<<gE16, tb>>>(pagg, src, dst, out, E);
}